// round 1
// baseline (speedup 1.0000x reference)
#include <cuda_runtime.h>
#include <math.h>

#define Bq 4
#define Sq 2048
#define DMq 512
#define Hq 8
#define Dq 64
#define BSq (Bq * Sq)          // 8192
#define Y_ELEMS ((size_t)Bq * Sq * DMq)          // 4,194,304
#define ATT_ELEMS ((size_t)Bq * Hq * Sq * Sq)    // 134,217,728

// Scratch (allocation-free rule: __device__ globals)
__device__ float g_q[Bq * Sq * DMq];
__device__ float g_k[Bq * Sq * DMq];
__device__ float g_v[Bq * Sq * DMq];
__device__ float g_ctx[Bq * Sq * DMq];

// ---------------------------------------------------------------------------
// Generic GEMM + bias: C[M,N] = A[M,K] @ W[K,N] + bias[N]
// 64x64 tile, BK=16, 256 threads, 4x4 per thread.
// ---------------------------------------------------------------------------
__global__ __launch_bounds__(256) void gemm_bias_kernel(
    const float* __restrict__ A, const float* __restrict__ W,
    const float* __restrict__ bias, float* __restrict__ C,
    int M, int N, int K)
{
    __shared__ float As[16][64];   // [k][m]
    __shared__ float Ws[16][64];   // [k][n]
    int tid = threadIdx.x;
    int tx = tid & 15, ty = tid >> 4;
    int m0 = blockIdx.y * 64;
    int n0 = blockIdx.x * 64;

    float acc[4][4] = {};

    for (int k0 = 0; k0 < K; k0 += 16) {
        // Load A tile 64x16 (transposed into As[k][m])
        {
            int row = tid >> 2;          // 0..63
            int seg = (tid & 3) * 4;     // 0,4,8,12
            float4 a = *reinterpret_cast<const float4*>(
                &A[(size_t)(m0 + row) * K + k0 + seg]);
            As[seg + 0][row] = a.x;
            As[seg + 1][row] = a.y;
            As[seg + 2][row] = a.z;
            As[seg + 3][row] = a.w;
        }
        // Load W tile 16x64
        {
            int row = tid >> 4;          // 0..15
            int col = (tid & 15) * 4;    // 0..60
            float4 w = *reinterpret_cast<const float4*>(
                &W[(size_t)(k0 + row) * N + n0 + col]);
            *reinterpret_cast<float4*>(&Ws[row][col]) = w;
        }
        __syncthreads();
#pragma unroll
        for (int kk = 0; kk < 16; kk++) {
            float a[4], b[4];
#pragma unroll
            for (int i = 0; i < 4; i++) a[i] = As[kk][ty * 4 + i];
#pragma unroll
            for (int j = 0; j < 4; j++) b[j] = Ws[kk][tx * 4 + j];
#pragma unroll
            for (int i = 0; i < 4; i++)
#pragma unroll
                for (int j = 0; j < 4; j++) acc[i][j] = fmaf(a[i], b[j], acc[i][j]);
        }
        __syncthreads();
    }

#pragma unroll
    for (int i = 0; i < 4; i++) {
        int m = m0 + ty * 4 + i;
#pragma unroll
        for (int j = 0; j < 4; j++) {
            int n = n0 + tx * 4 + j;
            C[(size_t)m * N + n] = acc[i][j] + bias[n];
        }
    }
}

// ---------------------------------------------------------------------------
// scores[bh, q, k] = 0.125 * dot(qh[q,:], kh[k,:]) + mask[b,k] * (-1e9)
// Per (b,h): Qh[2048,64] @ Kh[2048,64]^T. 64x64 output tile, K=64 single pass.
// ---------------------------------------------------------------------------
__global__ __launch_bounds__(256) void scores_kernel(
    const float* __restrict__ q, const float* __restrict__ k,
    const float* __restrict__ mask, float* __restrict__ att)
{
    int bh = blockIdx.z;            // b*H + h
    int b = bh >> 3, h = bh & 7;
    int q0 = blockIdx.y * 64;
    int n0 = blockIdx.x * 64;

    __shared__ float Qs[64][65];    // [q_row][d]
    __shared__ float Ks[64][65];    // [k_row][d]

    int tid = threadIdx.x;
    int tx = tid & 15, ty = tid >> 4;

    // Load tiles: 64 rows x 64 d each; 16 floats/thread
    {
        int row = tid >> 2;
        int cbase = (tid & 3) * 16;
        const float* qp = q + ((size_t)(b * Sq + q0 + row)) * DMq + h * Dq + cbase;
        const float* kp = k + ((size_t)(b * Sq + n0 + row)) * DMq + h * Dq + cbase;
#pragma unroll
        for (int c = 0; c < 16; c += 4) {
            float4 tq = *reinterpret_cast<const float4*>(qp + c);
            Qs[row][cbase + c + 0] = tq.x;
            Qs[row][cbase + c + 1] = tq.y;
            Qs[row][cbase + c + 2] = tq.z;
            Qs[row][cbase + c + 3] = tq.w;
            float4 tk = *reinterpret_cast<const float4*>(kp + c);
            Ks[row][cbase + c + 0] = tk.x;
            Ks[row][cbase + c + 1] = tk.y;
            Ks[row][cbase + c + 2] = tk.z;
            Ks[row][cbase + c + 3] = tk.w;
        }
    }
    __syncthreads();

    float acc[4][4] = {};
#pragma unroll 16
    for (int kk = 0; kk < 64; kk++) {
        float a[4], bb[4];
#pragma unroll
        for (int i = 0; i < 4; i++) a[i] = Qs[ty * 4 + i][kk];
#pragma unroll
        for (int j = 0; j < 4; j++) bb[j] = Ks[tx * 4 + j][kk];
#pragma unroll
        for (int i = 0; i < 4; i++)
#pragma unroll
            for (int j = 0; j < 4; j++) acc[i][j] = fmaf(a[i], bb[j], acc[i][j]);
    }

    float mval[4];
#pragma unroll
    for (int j = 0; j < 4; j++)
        mval[j] = mask[(size_t)b * Sq + n0 + tx * 4 + j] * -1e9f;

    float* out = att + ((size_t)bh * Sq + q0) * Sq + n0;
#pragma unroll
    for (int i = 0; i < 4; i++) {
        size_t rowoff = (size_t)(ty * 4 + i) * Sq;
#pragma unroll
        for (int j = 0; j < 4; j++)
            out[rowoff + tx * 4 + j] = acc[i][j] * 0.125f + mval[j];
    }
}

// ---------------------------------------------------------------------------
// In-place row softmax over S=2048. One block per row, 256 threads, 8 vals ea.
// ---------------------------------------------------------------------------
__global__ __launch_bounds__(256) void softmax_kernel(float* __restrict__ att)
{
    __shared__ float red[256];
    size_t row = blockIdx.x;
    float* p = att + row * Sq;
    int tid = threadIdx.x;

    float4 v0 = reinterpret_cast<float4*>(p)[tid * 2];
    float4 v1 = reinterpret_cast<float4*>(p)[tid * 2 + 1];

    float m = fmaxf(fmaxf(fmaxf(v0.x, v0.y), fmaxf(v0.z, v0.w)),
                    fmaxf(fmaxf(v1.x, v1.y), fmaxf(v1.z, v1.w)));
    red[tid] = m;
    __syncthreads();
    for (int s = 128; s > 0; s >>= 1) {
        if (tid < s) red[tid] = fmaxf(red[tid], red[tid + s]);
        __syncthreads();
    }
    m = red[0];
    __syncthreads();

    v0.x = __expf(v0.x - m); v0.y = __expf(v0.y - m);
    v0.z = __expf(v0.z - m); v0.w = __expf(v0.w - m);
    v1.x = __expf(v1.x - m); v1.y = __expf(v1.y - m);
    v1.z = __expf(v1.z - m); v1.w = __expf(v1.w - m);

    float s_loc = v0.x + v0.y + v0.z + v0.w + v1.x + v1.y + v1.z + v1.w;
    red[tid] = s_loc;
    __syncthreads();
    for (int s = 128; s > 0; s >>= 1) {
        if (tid < s) red[tid] += red[tid + s];
        __syncthreads();
    }
    float inv = 1.0f / red[0];

    v0.x *= inv; v0.y *= inv; v0.z *= inv; v0.w *= inv;
    v1.x *= inv; v1.y *= inv; v1.z *= inv; v1.w *= inv;
    reinterpret_cast<float4*>(p)[tid * 2] = v0;
    reinterpret_cast<float4*>(p)[tid * 2 + 1] = v1;
}

// ---------------------------------------------------------------------------
// ctx[b, q, h*64+d] = sum_k att[bh,q,k] * v[b,k,h*64+d]
// Per (b,h): [2048,2048] @ [2048,64]. 64 q-rows per block, full N=64.
// ---------------------------------------------------------------------------
__global__ __launch_bounds__(256) void ctx_kernel(
    const float* __restrict__ att, const float* __restrict__ v,
    float* __restrict__ ctx)
{
    int bh = blockIdx.z;
    int b = bh >> 3, h = bh & 7;
    int q0 = blockIdx.y * 64;

    __shared__ float As[64][65];   // att [q][k]
    __shared__ float Vs[64][65];   // v   [k][d]

    int tid = threadIdx.x;
    int tx = tid & 15, ty = tid >> 4;
    int row = tid >> 2;
    int cbase = (tid & 3) * 16;

    float acc[4][4] = {};
    const float* attp = att + ((size_t)bh * Sq + q0) * Sq;

    for (int k0 = 0; k0 < Sq; k0 += 64) {
        const float* ap = attp + (size_t)row * Sq + k0 + cbase;
        const float* vp = v + ((size_t)(b * Sq + k0 + row)) * DMq + h * Dq + cbase;
#pragma unroll
        for (int c = 0; c < 16; c += 4) {
            float4 ta = *reinterpret_cast<const float4*>(ap + c);
            As[row][cbase + c + 0] = ta.x;
            As[row][cbase + c + 1] = ta.y;
            As[row][cbase + c + 2] = ta.z;
            As[row][cbase + c + 3] = ta.w;
            float4 tv = *reinterpret_cast<const float4*>(vp + c);
            Vs[row][cbase + c + 0] = tv.x;
            Vs[row][cbase + c + 1] = tv.y;
            Vs[row][cbase + c + 2] = tv.z;
            Vs[row][cbase + c + 3] = tv.w;
        }
        __syncthreads();
#pragma unroll 16
        for (int kk = 0; kk < 64; kk++) {
            float a[4], bb[4];
#pragma unroll
            for (int i = 0; i < 4; i++) a[i] = As[ty * 4 + i][kk];
#pragma unroll
            for (int j = 0; j < 4; j++) bb[j] = Vs[kk][tx * 4 + j];
#pragma unroll
            for (int i = 0; i < 4; i++)
#pragma unroll
                for (int j = 0; j < 4; j++) acc[i][j] = fmaf(a[i], bb[j], acc[i][j]);
        }
        __syncthreads();
    }

#pragma unroll
    for (int i = 0; i < 4; i++) {
        size_t off = ((size_t)(b * Sq + q0 + ty * 4 + i)) * DMq + h * Dq;
#pragma unroll
        for (int j = 0; j < 4; j++)
            ctx[off + tx * 4 + j] = acc[i][j];
    }
}

// ---------------------------------------------------------------------------
extern "C" void kernel_launch(void* const* d_in, const int* in_sizes, int n_in,
                              void* d_out, int out_size)
{
    const float* Q    = (const float*)d_in[0];
    const float* K    = (const float*)d_in[1];
    const float* V    = (const float*)d_in[2];
    const float* mask = (const float*)d_in[3];
    const float* Wq   = (const float*)d_in[4];
    const float* bq   = (const float*)d_in[5];
    const float* Wk   = (const float*)d_in[6];
    const float* bk   = (const float*)d_in[7];
    const float* Wv   = (const float*)d_in[8];
    const float* bv   = (const float*)d_in[9];
    const float* Wo   = (const float*)d_in[10];
    const float* bo   = (const float*)d_in[11];

    float *qp, *kp, *vp, *cp;
    cudaGetSymbolAddress((void**)&qp, g_q);
    cudaGetSymbolAddress((void**)&kp, g_k);
    cudaGetSymbolAddress((void**)&vp, g_v);
    cudaGetSymbolAddress((void**)&cp, g_ctx);

    float* Y   = (float*)d_out;
    float* att = Y + Y_ELEMS;   // output layout: [Y | att_ws]

    dim3 gproj(DMq / 64, BSq / 64);            // (8, 128)
    gemm_bias_kernel<<<gproj, 256>>>(Q, Wq, bq, qp, BSq, DMq, DMq);
    gemm_bias_kernel<<<gproj, 256>>>(K, Wk, bk, kp, BSq, DMq, DMq);
    gemm_bias_kernel<<<gproj, 256>>>(V, Wv, bv, vp, BSq, DMq, DMq);

    dim3 gsc(Sq / 64, Sq / 64, Bq * Hq);       // (32, 32, 32)
    scores_kernel<<<gsc, 256>>>(qp, kp, mask, att);

    softmax_kernel<<<Bq * Hq * Sq, 256>>>(att);

    dim3 gctx(1, Sq / 64, Bq * Hq);            // (1, 32, 32)
    ctx_kernel<<<gctx, 256>>>(att, vp, cp);

    gemm_bias_kernel<<<gproj, 256>>>(cp, Wo, bo, Y, BSq, DMq, DMq);
}

// round 3
// speedup vs baseline: 1.7282x; 1.7282x over previous
#include <cuda_runtime.h>
#include <cuda_bf16.h>
#include <cstdint>
#include <math.h>

#define Bq 4
#define Sq 2048
#define DMq 512
#define Hq 8
#define BSq (Bq * Sq)
#define Y_ELEMS ((size_t)Bq * Sq * DMq)

// Scratch (__device__ globals; no allocation allowed)
__device__ __nv_bfloat16 g_qhi[Bq * Sq * DMq];
__device__ __nv_bfloat16 g_qlo[Bq * Sq * DMq];
__device__ __nv_bfloat16 g_khi[Bq * Sq * DMq];
__device__ __nv_bfloat16 g_klo[Bq * Sq * DMq];
__device__ __nv_bfloat16 g_vhi[Bq * Sq * DMq];
__device__ __nv_bfloat16 g_vlo[Bq * Sq * DMq];
__device__ float g_ctx[Bq * Sq * DMq];

// ---------------------------------------------------------------------------
// Warp-MMA helpers (sm_80-compatible: no 'a'-gated features)
// ---------------------------------------------------------------------------
__device__ __forceinline__ uint32_t smem_u32(const void* p) {
    uint32_t a;
    asm("{ .reg .u64 t; cvta.to.shared.u64 t, %1; cvt.u32.u64 %0, t; }"
        : "=r"(a) : "l"(p));
    return a;
}

__device__ __forceinline__ void ldsm_x4(uint32_t* r, uint32_t addr) {
    asm volatile("ldmatrix.sync.aligned.m8n8.x4.shared.b16 {%0,%1,%2,%3}, [%4];"
                 : "=r"(r[0]), "=r"(r[1]), "=r"(r[2]), "=r"(r[3]) : "r"(addr));
}

__device__ __forceinline__ void ldsm_x4_trans(uint32_t* r, uint32_t addr) {
    asm volatile("ldmatrix.sync.aligned.m8n8.x4.trans.shared.b16 {%0,%1,%2,%3}, [%4];"
                 : "=r"(r[0]), "=r"(r[1]), "=r"(r[2]), "=r"(r[3]) : "r"(addr));
}

__device__ __forceinline__ void mma_bf16(float* d, const uint32_t* a,
                                         uint32_t b0, uint32_t b1) {
    asm volatile(
        "mma.sync.aligned.m16n8k16.row.col.f32.bf16.bf16.f32 "
        "{%0,%1,%2,%3}, {%4,%5,%6,%7}, {%8,%9}, {%0,%1,%2,%3};"
        : "+f"(d[0]), "+f"(d[1]), "+f"(d[2]), "+f"(d[3])
        : "r"(a[0]), "r"(a[1]), "r"(a[2]), "r"(a[3]), "r"(b0), "r"(b1));
}

__device__ __forceinline__ uint32_t pack_bf16(float x, float y) {
    __nv_bfloat162 t = __floats2bfloat162_rn(x, y);
    return *reinterpret_cast<uint32_t*>(&t);
}

// ---------------------------------------------------------------------------
// Projection GEMM + bias, 128x128 tile, BK=16, 256 threads, 8x8/thread.
// Writes fp32 and/or bf16 hi/lo split.
// ---------------------------------------------------------------------------
__global__ __launch_bounds__(256) void gemm_bias128_kernel(
    const float* __restrict__ A, const float* __restrict__ W,
    const float* __restrict__ bias, float* __restrict__ Cf,
    __nv_bfloat16* __restrict__ Chi, __nv_bfloat16* __restrict__ Clo,
    int M, int N, int K)
{
    __shared__ float As[16][132];
    __shared__ float Ws[16][132];
    int tid = threadIdx.x;
    int ty = tid >> 4, tx = tid & 15;
    int m0 = blockIdx.y * 128, n0 = blockIdx.x * 128;

    float acc[8][8] = {};
    int lrow = tid >> 1;
    int lseg = (tid & 1) * 8;
    int wrow = tid >> 4;
    int wcol = (tid & 15) * 8;

    for (int k0 = 0; k0 < K; k0 += 16) {
        float4 a0 = *(const float4*)&A[(size_t)(m0 + lrow) * K + k0 + lseg];
        float4 a1 = *(const float4*)&A[(size_t)(m0 + lrow) * K + k0 + lseg + 4];
        As[lseg + 0][lrow] = a0.x; As[lseg + 1][lrow] = a0.y;
        As[lseg + 2][lrow] = a0.z; As[lseg + 3][lrow] = a0.w;
        As[lseg + 4][lrow] = a1.x; As[lseg + 5][lrow] = a1.y;
        As[lseg + 6][lrow] = a1.z; As[lseg + 7][lrow] = a1.w;
        float4 w0 = *(const float4*)&W[(size_t)(k0 + wrow) * N + n0 + wcol];
        float4 w1 = *(const float4*)&W[(size_t)(k0 + wrow) * N + n0 + wcol + 4];
        *(float4*)&Ws[wrow][wcol] = w0;
        *(float4*)&Ws[wrow][wcol + 4] = w1;
        __syncthreads();
#pragma unroll
        for (int kk = 0; kk < 16; kk++) {
            float4 af0 = *(float4*)&As[kk][ty * 8];
            float4 af1 = *(float4*)&As[kk][ty * 8 + 4];
            float4 bf0 = *(float4*)&Ws[kk][tx * 8];
            float4 bf1 = *(float4*)&Ws[kk][tx * 8 + 4];
            float a[8] = {af0.x, af0.y, af0.z, af0.w, af1.x, af1.y, af1.z, af1.w};
            float bb[8] = {bf0.x, bf0.y, bf0.z, bf0.w, bf1.x, bf1.y, bf1.z, bf1.w};
#pragma unroll
            for (int i = 0; i < 8; i++)
#pragma unroll
                for (int j = 0; j < 8; j++)
                    acc[i][j] = fmaf(a[i], bb[j], acc[i][j]);
        }
        __syncthreads();
    }

    float bv[8];
#pragma unroll
    for (int j = 0; j < 8; j++) bv[j] = bias[n0 + tx * 8 + j];

#pragma unroll
    for (int i = 0; i < 8; i++) {
        size_t row = (size_t)(m0 + ty * 8 + i);
#pragma unroll
        for (int j = 0; j < 8; j++) {
            size_t idx = row * N + n0 + tx * 8 + j;
            float val = acc[i][j] + bv[j];
            if (Cf) Cf[idx] = val;
            if (Chi) {
                __nv_bfloat16 hb = __float2bfloat16_rn(val);
                float rem = val - __bfloat162float(hb);
                Chi[idx] = hb;
                Clo[idx] = __float2bfloat16_rn(rem);
            }
        }
    }
}

// ---------------------------------------------------------------------------
// scores via mma.sync bf16x3: D[128q x 128k] per CTA.
// att = (Qhi*Khi' + Qhi*Klo' + Qlo*Khi') * 0.125 + mask * -1e9
// smem: 4 tiles of [128][72] bf16 (stride 144B, conflict-free ldmatrix)
// ---------------------------------------------------------------------------
#define SC_TILE_BYTES (128 * 144)
#define SC_SMEM_BYTES (4 * SC_TILE_BYTES)

__global__ __launch_bounds__(256) void scores_mma_kernel(
    const __nv_bfloat16* __restrict__ qhi, const __nv_bfloat16* __restrict__ qlo,
    const __nv_bfloat16* __restrict__ khi, const __nv_bfloat16* __restrict__ klo,
    const float* __restrict__ mask, float* __restrict__ att)
{
    extern __shared__ char sm[];
    char* bp = sm;
    uint32_t sb = smem_u32(sm);
    const uint32_t QHIo = 0, QLOo = SC_TILE_BYTES, KHIo = 2 * SC_TILE_BYTES,
                   KLOo = 3 * SC_TILE_BYTES;

    int tid = threadIdx.x;
    int lane = tid & 31, wid = tid >> 5;
    int wq = wid >> 1, wn = wid & 1;
    int bh = blockIdx.z, b = bh >> 3, h = bh & 7;
    int q0 = blockIdx.y * 128;
    int n0 = blockIdx.x * 128;

    // Load Q and K tiles (128 rows x 64 bf16 each, hi+lo)
    for (int it = tid; it < 1024; it += 256) {
        int row = it >> 3, ch = it & 7;
        int so = row * 144 + ch * 16;
        size_t gq = ((size_t)(b * Sq + q0 + row)) * DMq + h * 64 + ch * 8;
        size_t gk = ((size_t)(b * Sq + n0 + row)) * DMq + h * 64 + ch * 8;
        *(uint4*)(bp + QHIo + so) = *(const uint4*)(qhi + gq);
        *(uint4*)(bp + QLOo + so) = *(const uint4*)(qlo + gq);
        *(uint4*)(bp + KHIo + so) = *(const uint4*)(khi + gk);
        *(uint4*)(bp + KLOo + so) = *(const uint4*)(klo + gk);
    }
    __syncthreads();

    float acc[2][8][4] = {};

    const uint32_t Aoff[3] = {QHIo, QHIo, QLOo};
    const uint32_t Boff[3] = {KHIo, KLOo, KHIo};

#pragma unroll
    for (int p = 0; p < 3; p++) {
        uint32_t abase = sb + Aoff[p] + (wq * 32) * 144;
        uint32_t bbase = sb + Boff[p] + (wn * 64) * 144;
        uint32_t arow = lane & 15;
        uint32_t acolb = (lane >> 4) * 16;
#pragma unroll
        for (int kt = 0; kt < 4; kt++) {
            uint32_t a0[4], a1[4];
            ldsm_x4(a0, abase + arow * 144 + acolb + kt * 32);
            ldsm_x4(a1, abase + (16 + arow) * 144 + acolb + kt * 32);
            uint32_t brow = (lane & 7) + ((lane & 16) ? 8 : 0);
            uint32_t bcolb = ((lane >> 3) & 1) * 16 + kt * 32;
#pragma unroll
            for (int np = 0; np < 4; np++) {
                uint32_t bb[4];
                ldsm_x4(bb, bbase + (brow + np * 16) * 144 + bcolb);
                mma_bf16(acc[0][np * 2 + 0], a0, bb[0], bb[1]);
                mma_bf16(acc[0][np * 2 + 1], a0, bb[2], bb[3]);
                mma_bf16(acc[1][np * 2 + 0], a1, bb[0], bb[1]);
                mma_bf16(acc[1][np * 2 + 1], a1, bb[2], bb[3]);
            }
        }
    }

    // Epilogue
    int g = lane >> 2, tg = lane & 3;
#pragma unroll
    for (int ni = 0; ni < 8; ni++) {
        int col = n0 + wn * 64 + ni * 8 + tg * 2;
        float2 mv = *(const float2*)&mask[(size_t)b * Sq + col];
        float mx = mv.x * -1e9f, my = mv.y * -1e9f;
#pragma unroll
        for (int mi = 0; mi < 2; mi++) {
            int row = q0 + wq * 32 + mi * 16 + g;
            float2 o;
            o.x = acc[mi][ni][0] * 0.125f + mx;
            o.y = acc[mi][ni][1] * 0.125f + my;
            *(float2*)&att[((size_t)bh * Sq + row) * Sq + col] = o;
            o.x = acc[mi][ni][2] * 0.125f + mx;
            o.y = acc[mi][ni][3] * 0.125f + my;
            *(float2*)&att[((size_t)bh * Sq + row + 8) * Sq + col] = o;
        }
    }
}

// ---------------------------------------------------------------------------
// Row softmax over S=2048, in place.
// ---------------------------------------------------------------------------
__global__ __launch_bounds__(256) void softmax_kernel(float* __restrict__ att)
{
    __shared__ float red[256];
    size_t row = blockIdx.x;
    float* p = att + row * Sq;
    int tid = threadIdx.x;

    float4 v0 = reinterpret_cast<float4*>(p)[tid * 2];
    float4 v1 = reinterpret_cast<float4*>(p)[tid * 2 + 1];

    float m = fmaxf(fmaxf(fmaxf(v0.x, v0.y), fmaxf(v0.z, v0.w)),
                    fmaxf(fmaxf(v1.x, v1.y), fmaxf(v1.z, v1.w)));
    red[tid] = m;
    __syncthreads();
    for (int s = 128; s > 0; s >>= 1) {
        if (tid < s) red[tid] = fmaxf(red[tid], red[tid + s]);
        __syncthreads();
    }
    m = red[0];
    __syncthreads();

    v0.x = __expf(v0.x - m); v0.y = __expf(v0.y - m);
    v0.z = __expf(v0.z - m); v0.w = __expf(v0.w - m);
    v1.x = __expf(v1.x - m); v1.y = __expf(v1.y - m);
    v1.z = __expf(v1.z - m); v1.w = __expf(v1.w - m);

    float s_loc = v0.x + v0.y + v0.z + v0.w + v1.x + v1.y + v1.z + v1.w;
    red[tid] = s_loc;
    __syncthreads();
    for (int s = 128; s > 0; s >>= 1) {
        if (tid < s) red[tid] += red[tid + s];
        __syncthreads();
    }
    float inv = 1.0f / red[0];

    v0.x *= inv; v0.y *= inv; v0.z *= inv; v0.w *= inv;
    v1.x *= inv; v1.y *= inv; v1.z *= inv; v1.w *= inv;
    reinterpret_cast<float4*>(p)[tid * 2] = v0;
    reinterpret_cast<float4*>(p)[tid * 2 + 1] = v1;
}

// ---------------------------------------------------------------------------
// ctx = att @ V via mma.sync bf16x3. 128q x 64d per CTA per (b,h).
// att fp32 tile -> hi/lo bf16 in smem on the fly; V pre-split.
// smem: Ahi/Alo [128][72] bf16, Vhi/Vlo [64][72] bf16
// ---------------------------------------------------------------------------
#define CTX_A_BYTES (128 * 144)
#define CTX_V_BYTES (64 * 144)
#define CTX_SMEM_BYTES (2 * CTX_A_BYTES + 2 * CTX_V_BYTES)

__global__ __launch_bounds__(256) void ctx_mma_kernel(
    const float* __restrict__ att,
    const __nv_bfloat16* __restrict__ vhi, const __nv_bfloat16* __restrict__ vlo,
    float* __restrict__ ctx)
{
    extern __shared__ char sm[];
    char* bp = sm;
    uint32_t sb = smem_u32(sm);
    const uint32_t AHIo = 0, ALOo = CTX_A_BYTES,
                   VHIo = 2 * CTX_A_BYTES, VLOo = 2 * CTX_A_BYTES + CTX_V_BYTES;

    int tid = threadIdx.x;
    int lane = tid & 31, wid = tid >> 5;
    int bh = blockIdx.y, b = bh >> 3, h = bh & 7;
    int q0 = blockIdx.x * 128;

    float acc[8][4] = {};

    for (int k0 = 0; k0 < Sq; k0 += 64) {
        // att 128x64 fp32 -> hi/lo bf16
        for (int it = tid; it < 2048; it += 256) {
            int row = it >> 4, c4 = (it & 15) * 4;
            float4 t = *(const float4*)&att[((size_t)bh * Sq + q0 + row) * Sq + k0 + c4];
            __nv_bfloat16 h0 = __float2bfloat16_rn(t.x);
            __nv_bfloat16 h1 = __float2bfloat16_rn(t.y);
            __nv_bfloat16 h2 = __float2bfloat16_rn(t.z);
            __nv_bfloat16 h3 = __float2bfloat16_rn(t.w);
            uint2 hp, lp;
            hp.x = pack_bf16(__bfloat162float(h0), __bfloat162float(h1));
            hp.y = pack_bf16(__bfloat162float(h2), __bfloat162float(h3));
            // repack exact hi bits (pack_bf16 re-rounds; hi values are exact bf16)
            lp.x = pack_bf16(t.x - __bfloat162float(h0), t.y - __bfloat162float(h1));
            lp.y = pack_bf16(t.z - __bfloat162float(h2), t.w - __bfloat162float(h3));
            int so = row * 144 + c4 * 2;
            *(uint2*)(bp + AHIo + so) = hp;
            *(uint2*)(bp + ALOo + so) = lp;
        }
        // V 64x64 hi/lo
        for (int it = tid; it < 512; it += 256) {
            int row = it >> 3, ch = it & 7;
            int so = row * 144 + ch * 16;
            size_t gv = ((size_t)(b * Sq + k0 + row)) * DMq + h * 64 + ch * 8;
            *(uint4*)(bp + VHIo + so) = *(const uint4*)(vhi + gv);
            *(uint4*)(bp + VLOo + so) = *(const uint4*)(vlo + gv);
        }
        __syncthreads();

        const uint32_t Aoff[3] = {AHIo, ALOo, AHIo};
        const uint32_t Boff[3] = {VHIo, VHIo, VLOo};
#pragma unroll
        for (int p = 0; p < 3; p++) {
            uint32_t abase = sb + Aoff[p] + (wid * 16) * 144;
            uint32_t bbase = sb + Boff[p];
            uint32_t arow = lane & 15;
            uint32_t acolb = (lane >> 4) * 16;
            uint32_t brow = (lane & 7) + ((lane & 8) ? 8 : 0);
            uint32_t bcolb = (lane & 16) ? 16 : 0;
#pragma unroll
            for (int kt = 0; kt < 4; kt++) {
                uint32_t a0[4];
                ldsm_x4(a0, abase + arow * 144 + acolb + kt * 32);
#pragma unroll
                for (int np = 0; np < 4; np++) {
                    uint32_t bb[4];
                    ldsm_x4_trans(bb, bbase + (kt * 16 + brow) * 144 + np * 32 + bcolb);
                    mma_bf16(acc[np * 2 + 0], a0, bb[0], bb[1]);
                    mma_bf16(acc[np * 2 + 1], a0, bb[2], bb[3]);
                }
            }
        }
        __syncthreads();
    }

    int g = lane >> 2, tg = lane & 3;
#pragma unroll
    for (int ni = 0; ni < 8; ni++) {
        int col = h * 64 + ni * 8 + tg * 2;
        int row = q0 + wid * 16 + g;
        float2 o;
        o.x = acc[ni][0]; o.y = acc[ni][1];
        *(float2*)&ctx[(size_t)(b * Sq + row) * DMq + col] = o;
        o.x = acc[ni][2]; o.y = acc[ni][3];
        *(float2*)&ctx[(size_t)(b * Sq + row + 8) * DMq + col] = o;
    }
}

// ---------------------------------------------------------------------------
extern "C" void kernel_launch(void* const* d_in, const int* in_sizes, int n_in,
                              void* d_out, int out_size)
{
    const float* Q    = (const float*)d_in[0];
    const float* K    = (const float*)d_in[1];
    const float* V    = (const float*)d_in[2];
    const float* mask = (const float*)d_in[3];
    const float* Wq   = (const float*)d_in[4];
    const float* bq   = (const float*)d_in[5];
    const float* Wk   = (const float*)d_in[6];
    const float* bk   = (const float*)d_in[7];
    const float* Wv   = (const float*)d_in[8];
    const float* bv   = (const float*)d_in[9];
    const float* Wo   = (const float*)d_in[10];
    const float* bo   = (const float*)d_in[11];

    __nv_bfloat16 *qhi, *qlo, *khi, *klo, *vhi, *vlo;
    float *cp;
    cudaGetSymbolAddress((void**)&qhi, g_qhi);
    cudaGetSymbolAddress((void**)&qlo, g_qlo);
    cudaGetSymbolAddress((void**)&khi, g_khi);
    cudaGetSymbolAddress((void**)&klo, g_klo);
    cudaGetSymbolAddress((void**)&vhi, g_vhi);
    cudaGetSymbolAddress((void**)&vlo, g_vlo);
    cudaGetSymbolAddress((void**)&cp, g_ctx);

    float* Y   = (float*)d_out;
    float* att = Y + Y_ELEMS;

    cudaFuncSetAttribute(scores_mma_kernel,
                         cudaFuncAttributeMaxDynamicSharedMemorySize, SC_SMEM_BYTES);
    cudaFuncSetAttribute(ctx_mma_kernel,
                         cudaFuncAttributeMaxDynamicSharedMemorySize, CTX_SMEM_BYTES);

    dim3 gproj(DMq / 128, BSq / 128);   // (4, 64)
    gemm_bias128_kernel<<<gproj, 256>>>(Q, Wq, bq, nullptr, qhi, qlo, BSq, DMq, DMq);
    gemm_bias128_kernel<<<gproj, 256>>>(K, Wk, bk, nullptr, khi, klo, BSq, DMq, DMq);
    gemm_bias128_kernel<<<gproj, 256>>>(V, Wv, bv, nullptr, vhi, vlo, BSq, DMq, DMq);

    dim3 gsc(Sq / 128, Sq / 128, Bq * Hq);  // (16, 16, 32)
    scores_mma_kernel<<<gsc, 256, SC_SMEM_BYTES>>>(qhi, qlo, khi, klo, mask, att);

    softmax_kernel<<<Bq * Hq * Sq, 256>>>(att);

    dim3 gctx(Sq / 128, Bq * Hq);           // (16, 32)
    ctx_mma_kernel<<<gctx, 256, CTX_SMEM_BYTES>>>(att, vhi, vlo, cp);

    gemm_bias128_kernel<<<gproj, 256>>>(cp, Wo, bo, Y, nullptr, nullptr, BSq, DMq, DMq);
}